// round 3
// baseline (speedup 1.0000x reference)
#include <cuda_runtime.h>
#include <cstdint>

// Problem constants
#define S_LEN  2048
#define EMBED  2048
#define NHEAD  32
#define NKV    8
#define HDIM   64
#define BATCH  2
#define MROWS  (BATCH * S_LEN)     // 4096
#define KV_N   (NKV * HDIM)        // 512

// Output buffer layout: [out (B,S,E)] [next_k (B,NKV,S,D)] [next_v (B,NKV,S,D)]
#define OFF_K  8388608
#define OFF_V  10485760

// Scratch (allocation-free rule: __device__ globals)
__device__ float g_Q[MROWS * EMBED];   // rope'd Q in (b,s,h,d) layout
__device__ float g_O[MROWS * EMBED];   // attention output in (b,s,h,d) layout

// ---------------------------------------------------------------------------
// SGEMM: C[M,N] = A[M,K] @ B[K,N], fp32, 128x128x16 tile, 256 threads, 8x8/thread
// mode 0: plain row-major store. mode 1: remap (m=b*S+s, n=kv*64+d) -> (b,kv,s,d)
// ---------------------------------------------------------------------------
#define BM 128
#define BN 128
#define BK 16
#define LDA 132
#define LDB 132

__global__ void __launch_bounds__(256) sgemm_kernel(
    const float* __restrict__ A, const float* __restrict__ Bw,
    float* __restrict__ C, int N, int K, int mode)
{
    __shared__ float As[BK * LDA];
    __shared__ float Bs[BK * LDB];

    const int tid = threadIdx.x;
    const int bm = blockIdx.y * BM;
    const int bn = blockIdx.x * BN;
    const int tx = tid & 15;
    const int ty = tid >> 4;

    const int arow = tid >> 2;          // 0..63
    const int acol = (tid & 3) * 4;     // 0,4,8,12
    const int brow = tid >> 5;          // 0..7
    const int bcol = (tid & 31) * 4;    // 0..124

    const float* Ap = A + (size_t)(bm + arow) * K + acol;
    const float* Bp = Bw + (size_t)brow * N + bn + bcol;

    float acc[8][8];
#pragma unroll
    for (int i = 0; i < 8; i++)
#pragma unroll
        for (int j = 0; j < 8; j++) acc[i][j] = 0.0f;

    for (int k0 = 0; k0 < K; k0 += BK) {
        float4 a0 = *(const float4*)Ap;
        float4 a1 = *(const float4*)(Ap + (size_t)64 * K);
        float4 b0 = *(const float4*)Bp;
        float4 b1 = *(const float4*)(Bp + (size_t)8 * N);
        Ap += BK;
        Bp += (size_t)BK * N;

        // A stored transposed: As[k][m]
        As[(acol + 0) * LDA + arow] = a0.x;
        As[(acol + 1) * LDA + arow] = a0.y;
        As[(acol + 2) * LDA + arow] = a0.z;
        As[(acol + 3) * LDA + arow] = a0.w;
        As[(acol + 0) * LDA + arow + 64] = a1.x;
        As[(acol + 1) * LDA + arow + 64] = a1.y;
        As[(acol + 2) * LDA + arow + 64] = a1.z;
        As[(acol + 3) * LDA + arow + 64] = a1.w;
        *(float4*)&Bs[brow * LDB + bcol] = b0;
        *(float4*)&Bs[(brow + 8) * LDB + bcol] = b1;
        __syncthreads();

#pragma unroll
        for (int k = 0; k < BK; k++) {
            float4 av0 = *(float4*)&As[k * LDA + ty * 8];
            float4 av1 = *(float4*)&As[k * LDA + ty * 8 + 4];
            float4 bv0 = *(float4*)&Bs[k * LDB + tx * 8];
            float4 bv1 = *(float4*)&Bs[k * LDB + tx * 8 + 4];
            float a[8] = {av0.x, av0.y, av0.z, av0.w, av1.x, av1.y, av1.z, av1.w};
            float b[8] = {bv0.x, bv0.y, bv0.z, bv0.w, bv1.x, bv1.y, bv1.z, bv1.w};
#pragma unroll
            for (int i = 0; i < 8; i++)
#pragma unroll
                for (int j = 0; j < 8; j++) acc[i][j] += a[i] * b[j];
        }
        __syncthreads();
    }

    // Epilogue
    if (mode == 0) {
#pragma unroll
        for (int i = 0; i < 8; i++) {
            int m = bm + ty * 8 + i;
            float* dst = C + (size_t)m * N + bn + tx * 8;
            *(float4*)dst       = make_float4(acc[i][0], acc[i][1], acc[i][2], acc[i][3]);
            *(float4*)(dst + 4) = make_float4(acc[i][4], acc[i][5], acc[i][6], acc[i][7]);
        }
    } else {
        // n = kv*64 + d ; m = b*S + s ; dst (b,kv,s,d)
        int n0 = bn + tx * 8;
        int kv = n0 >> 6;
        int d0 = n0 & 63;
#pragma unroll
        for (int i = 0; i < 8; i++) {
            int m = bm + ty * 8 + i;
            int b = m >> 11;
            int s = m & (S_LEN - 1);
            float* dst = C + (((size_t)(b * NKV + kv) * S_LEN + s) * HDIM) + d0;
            *(float4*)dst       = make_float4(acc[i][0], acc[i][1], acc[i][2], acc[i][3]);
            *(float4*)(dst + 4) = make_float4(acc[i][4], acc[i][5], acc[i][6], acc[i][7]);
        }
    }
}

// ---------------------------------------------------------------------------
// RoPE (in-place). Q layout (b,s,h,d); K layout (b,kv,s,d).
// cos/sin: (S, 64), with cos[s, d] == cos[s, d+32].
// ---------------------------------------------------------------------------
__global__ void rope_q_kernel(float* __restrict__ Q,
                              const float* __restrict__ cosb,
                              const float* __restrict__ sinb)
{
    int idx = blockIdx.x * blockDim.x + threadIdx.x;  // M*NH*32 threads
    int d = idx & 31;
    int h = (idx >> 5) & 31;
    int m = idx >> 10;            // 0..4095
    int s = m & (S_LEN - 1);
    float c = cosb[s * HDIM + d];
    float sn = sinb[s * HDIM + d];
    float* base = Q + (size_t)m * EMBED + h * HDIM;
    float x1 = base[d];
    float x2 = base[d + 32];
    base[d]      = x1 * c - x2 * sn;
    base[d + 32] = x2 * c + x1 * sn;
}

__global__ void rope_k_kernel(float* __restrict__ Kb,
                              const float* __restrict__ cosb,
                              const float* __restrict__ sinb)
{
    int idx = blockIdx.x * blockDim.x + threadIdx.x;  // B*NKV*S*32 threads
    int d = idx & 31;
    int s = (idx >> 5) & (S_LEN - 1);
    int kvb = idx >> 16;          // b*NKV + kv, 0..15
    float c = cosb[s * HDIM + d];
    float sn = sinb[s * HDIM + d];
    float* base = Kb + ((size_t)kvb * S_LEN + s) * HDIM;
    float x1 = base[d];
    float x2 = base[d + 32];
    base[d]      = x1 * c - x2 * sn;
    base[d + 32] = x2 * c + x1 * sn;
}

// ---------------------------------------------------------------------------
// Flash attention, fp32, causal. 64 q-rows x 64 keys per tile, 256 threads.
// Thread (ty 0..15, tx 0..15): rows 4ty..+3, cols 4tx..+3 (keys for S, dims for O).
// Row stats kept redundantly in all 16 lanes of each row group (shfl width 16).
// smem: Qs | Ks(=Ps alias) | Vs, each 64x68 floats -> 52224 B dynamic.
// ---------------------------------------------------------------------------
#define ATT_PAD 68
#define ATT_SMEM (3 * 64 * ATT_PAD * 4)

__global__ void __launch_bounds__(256) attn_kernel(
    const float* __restrict__ Q, const float* __restrict__ Kb,
    const float* __restrict__ Vb, float* __restrict__ O)
{
    extern __shared__ float sm[];
    float* Qs = sm;
    float* Ks = sm + 64 * ATT_PAD;      // also holds P after softmax
    float* Vs = sm + 2 * 64 * ATT_PAD;

    const int tid = threadIdx.x;
    const int tx = tid & 15;
    const int ty = tid >> 4;
    const int qtile = blockIdx.x;       // 0..31
    const int h = blockIdx.y;           // 0..31
    const int b = blockIdx.z;           // 0..1
    const int kv = h >> 2;
    const int s0 = qtile * 64;

    const float* Qbase = Q + (size_t)b * S_LEN * EMBED + (size_t)h * HDIM;
    const float* Kbase = Kb + (size_t)(b * NKV + kv) * S_LEN * HDIM;
    const float* Vbase = Vb + (size_t)(b * NKV + kv) * S_LEN * HDIM;

    // Load Q tile (rows s0..s0+63) into Qs[r][d]
#pragma unroll
    for (int it = 0; it < 4; it++) {
        int f = tid + it * 256;
        int r = f >> 4;
        int c4 = (f & 15) * 4;
        *(float4*)&Qs[r * ATT_PAD + c4] =
            *(const float4*)(Qbase + (size_t)(s0 + r) * EMBED + c4);
    }

    float m_i[4], l_i[4], o_acc[4][4];
#pragma unroll
    for (int i = 0; i < 4; i++) {
        m_i[i] = -1e30f;
        l_i[i] = 0.0f;
#pragma unroll
        for (int j = 0; j < 4; j++) o_acc[i][j] = 0.0f;
    }

    for (int jt = 0; jt <= qtile; jt++) {
        // Load K and V tiles (contiguous (s,d) rows)
#pragma unroll
        for (int it = 0; it < 4; it++) {
            int f = tid + it * 256;
            int r = f >> 4;
            int c4 = (f & 15) * 4;
            *(float4*)&Ks[r * ATT_PAD + c4] =
                *(const float4*)(Kbase + (size_t)(jt * 64 + r) * HDIM + c4);
            *(float4*)&Vs[r * ATT_PAD + c4] =
                *(const float4*)(Vbase + (size_t)(jt * 64 + r) * HDIM + c4);
        }
        __syncthreads();

        // Scores: sc[i][j] = Q[4ty+i] . K[4tx+j]
        float sc[4][4];
#pragma unroll
        for (int i = 0; i < 4; i++)
#pragma unroll
            for (int j = 0; j < 4; j++) sc[i][j] = 0.0f;

#pragma unroll
        for (int kk = 0; kk < 16; kk++) {
            float4 a[4], bv[4];
#pragma unroll
            for (int i = 0; i < 4; i++)
                a[i] = *(float4*)&Qs[(ty * 4 + i) * ATT_PAD + kk * 4];
#pragma unroll
            for (int j = 0; j < 4; j++)
                bv[j] = *(float4*)&Ks[(tx * 4 + j) * ATT_PAD + kk * 4];
#pragma unroll
            for (int i = 0; i < 4; i++)
#pragma unroll
                for (int j = 0; j < 4; j++)
                    sc[i][j] += a[i].x * bv[j].x + a[i].y * bv[j].y +
                                a[i].z * bv[j].z + a[i].w * bv[j].w;
        }

        // Scale + causal mask (mask needed only on diagonal tile)
        const float scale = 0.125f;  // 1/sqrt(64)
        if (jt == qtile) {
#pragma unroll
            for (int i = 0; i < 4; i++) {
                int srow = s0 + ty * 4 + i;
#pragma unroll
                for (int j = 0; j < 4; j++) {
                    int tcol = jt * 64 + tx * 4 + j;
                    sc[i][j] = (tcol > srow) ? -1e30f : sc[i][j] * scale;
                }
            }
        } else {
#pragma unroll
            for (int i = 0; i < 4; i++)
#pragma unroll
                for (int j = 0; j < 4; j++) sc[i][j] *= scale;
        }

        // Online softmax per row (redundant across the 16 tx lanes of the row)
#pragma unroll
        for (int i = 0; i < 4; i++) {
            float rm = fmaxf(fmaxf(sc[i][0], sc[i][1]), fmaxf(sc[i][2], sc[i][3]));
            rm = fmaxf(rm, __shfl_xor_sync(0xffffffffu, rm, 1));
            rm = fmaxf(rm, __shfl_xor_sync(0xffffffffu, rm, 2));
            rm = fmaxf(rm, __shfl_xor_sync(0xffffffffu, rm, 4));
            rm = fmaxf(rm, __shfl_xor_sync(0xffffffffu, rm, 8));
            float mnew = fmaxf(m_i[i], rm);
            float corr = __expf(m_i[i] - mnew);
            float rs = 0.0f;
#pragma unroll
            for (int j = 0; j < 4; j++) {
                float p = __expf(sc[i][j] - mnew);
                sc[i][j] = p;
                rs += p;
            }
            rs += __shfl_xor_sync(0xffffffffu, rs, 1);
            rs += __shfl_xor_sync(0xffffffffu, rs, 2);
            rs += __shfl_xor_sync(0xffffffffu, rs, 4);
            rs += __shfl_xor_sync(0xffffffffu, rs, 8);
            l_i[i] = l_i[i] * corr + rs;
            m_i[i] = mnew;
#pragma unroll
            for (int j = 0; j < 4; j++) o_acc[i][j] *= corr;
        }

        __syncthreads();  // all lanes done reading Ks as K
        // Write P over Ks
#pragma unroll
        for (int i = 0; i < 4; i++)
            *(float4*)&Ks[(ty * 4 + i) * ATT_PAD + tx * 4] =
                make_float4(sc[i][0], sc[i][1], sc[i][2], sc[i][3]);
        __syncthreads();

        // O += P @ V : rows 4ty..+3, dims 4tx..+3
#pragma unroll
        for (int t4 = 0; t4 < 16; t4++) {
            float4 a[4], bv[4];
#pragma unroll
            for (int i = 0; i < 4; i++)
                a[i] = *(float4*)&Ks[(ty * 4 + i) * ATT_PAD + t4 * 4];
#pragma unroll
            for (int tt = 0; tt < 4; tt++)
                bv[tt] = *(float4*)&Vs[(t4 * 4 + tt) * ATT_PAD + tx * 4];
#pragma unroll
            for (int i = 0; i < 4; i++) {
                o_acc[i][0] += a[i].x * bv[0].x + a[i].y * bv[1].x + a[i].z * bv[2].x + a[i].w * bv[3].x;
                o_acc[i][1] += a[i].x * bv[0].y + a[i].y * bv[1].y + a[i].z * bv[2].y + a[i].w * bv[3].y;
                o_acc[i][2] += a[i].x * bv[0].z + a[i].y * bv[1].z + a[i].z * bv[2].z + a[i].w * bv[3].z;
                o_acc[i][3] += a[i].x * bv[0].w + a[i].y * bv[1].w + a[i].z * bv[2].w + a[i].w * bv[3].w;
            }
        }
        __syncthreads();  // before next tile overwrites Ks/Vs
    }

    // Epilogue: O[(b,s,h,d)] = o_acc / l
#pragma unroll
    for (int i = 0; i < 4; i++) {
        int srow = s0 + ty * 4 + i;
        float inv = 1.0f / l_i[i];
        float* dst = O + ((size_t)(b * S_LEN + srow) * EMBED) + h * HDIM + tx * 4;
        *(float4*)dst = make_float4(o_acc[i][0] * inv, o_acc[i][1] * inv,
                                    o_acc[i][2] * inv, o_acc[i][3] * inv);
    }
}

// ---------------------------------------------------------------------------
extern "C" void kernel_launch(void* const* d_in, const int* in_sizes, int n_in,
                              void* d_out, int out_size)
{
    const float* x    = (const float*)d_in[0];
    // d_in[1] = mask (bool) — causal mask is known statically, unused
    const float* cosb = (const float*)d_in[2];
    const float* sinb = (const float*)d_in[3];
    const float* Wq   = (const float*)d_in[4];
    const float* Wk   = (const float*)d_in[5];
    const float* Wv   = (const float*)d_in[6];
    const float* Wo   = (const float*)d_in[7];

    float* out  = (float*)d_out;
    float* kout = out + OFF_K;
    float* vout = out + OFF_V;

    float* gQ = nullptr;
    float* gO = nullptr;
    cudaGetSymbolAddress((void**)&gQ, g_Q);
    cudaGetSymbolAddress((void**)&gO, g_O);

    dim3 gQKV_q(EMBED / BN, MROWS / BM);   // (16, 32)
    dim3 gKV(KV_N / BN, MROWS / BM);       // (4, 32)

    // Projections
    sgemm_kernel<<<gQKV_q, 256>>>(x, Wq, gQ, EMBED, EMBED, 0);
    sgemm_kernel<<<gKV, 256>>>(x, Wk, kout, KV_N, EMBED, 1);
    sgemm_kernel<<<gKV, 256>>>(x, Wv, vout, KV_N, EMBED, 1);

    // RoPE in place
    rope_q_kernel<<<(MROWS * NHEAD * 32) / 256, 256>>>(gQ, cosb, sinb);
    rope_k_kernel<<<(BATCH * NKV * S_LEN * 32) / 256, 256>>>(kout, cosb, sinb);

    // Attention
    static bool attr_set = false;
    cudaFuncSetAttribute(attn_kernel, cudaFuncAttributeMaxDynamicSharedMemorySize, ATT_SMEM);
    (void)attr_set;
    attn_kernel<<<dim3(S_LEN / 64, NHEAD, BATCH), 256, ATT_SMEM>>>(gQ, kout, vout, gO);

    // Output projection
    sgemm_kernel<<<gQKV_q, 256>>>(gO, Wo, out, EMBED, EMBED, 0);
}

// round 5
// speedup vs baseline: 1.5649x; 1.5649x over previous
#include <cuda_runtime.h>
#include <cuda_bf16.h>
#include <cstdint>

// Problem constants
#define S_LEN  2048
#define EMBED  2048
#define NHEAD  32
#define NKV    8
#define HDIM   64
#define BATCH  2
#define MROWS  (BATCH * S_LEN)     // 4096
#define KV_N   (NKV * HDIM)        // 512

// Output buffer layout: [out (B,S,E)] [next_k (B,NKV,S,D)] [next_v (B,NKV,S,D)]
#define OFF_K  8388608
#define OFF_V  10485760

// ---------------------------------------------------------------------------
// Scratch (__device__ globals; allocation-free rule)
// ---------------------------------------------------------------------------
__device__ float g_Q[MROWS * EMBED];   // rope'd Q in (b,s,h,d) layout (fp32)
__device__ float g_O[MROWS * EMBED];   // attention output (b,s,h,d) (fp32)

__device__ __nv_bfloat16 g_xh[MROWS * EMBED];
__device__ __nv_bfloat16 g_xl[MROWS * EMBED];
__device__ __nv_bfloat16 g_oh[MROWS * EMBED];
__device__ __nv_bfloat16 g_ol[MROWS * EMBED];
__device__ __nv_bfloat16 g_wqt_h[EMBED * EMBED];   // Wq^T [N][K]
__device__ __nv_bfloat16 g_wqt_l[EMBED * EMBED];
__device__ __nv_bfloat16 g_wkt_h[KV_N * EMBED];
__device__ __nv_bfloat16 g_wkt_l[KV_N * EMBED];
__device__ __nv_bfloat16 g_wvt_h[KV_N * EMBED];
__device__ __nv_bfloat16 g_wvt_l[KV_N * EMBED];
__device__ __nv_bfloat16 g_wot_h[EMBED * EMBED];
__device__ __nv_bfloat16 g_wot_l[EMBED * EMBED];

// ---------------------------------------------------------------------------
// Portable (base-arch) PTX helpers: cp.async + ldmatrix + mma.sync (bf16)
// ---------------------------------------------------------------------------
__device__ __forceinline__ uint32_t smem_u32(const void* p) {
    uint32_t a;
    asm("{ .reg .u64 t; cvta.to.shared.u64 t, %1; cvt.u32.u64 %0, t; }" : "=r"(a) : "l"(p));
    return a;
}

#define CP_ASYNC16(dst, src) \
    asm volatile("cp.async.cg.shared.global [%0], [%1], 16;" :: "r"(dst), "l"(src))
#define CP_COMMIT() asm volatile("cp.async.commit_group;" ::: "memory")
#define CP_WAIT0()  asm volatile("cp.async.wait_group 0;" ::: "memory")
#define CP_WAIT1()  asm volatile("cp.async.wait_group 1;" ::: "memory")

#define LDSM4(r, addr) \
    asm volatile("ldmatrix.sync.aligned.m8n8.x4.shared.b16 {%0,%1,%2,%3}, [%4];" \
        : "=r"((r)[0]), "=r"((r)[1]), "=r"((r)[2]), "=r"((r)[3]) : "r"(addr))

#define MMA16816(d, a, b0, b1) \
    asm volatile("mma.sync.aligned.m16n8k16.row.col.f32.bf16.bf16.f32 " \
        "{%0,%1,%2,%3}, {%4,%5,%6,%7}, {%8,%9}, {%0,%1,%2,%3};" \
        : "+f"((d)[0]), "+f"((d)[1]), "+f"((d)[2]), "+f"((d)[3]) \
        : "r"((a)[0]), "r"((a)[1]), "r"((a)[2]), "r"((a)[3]), "r"(b0), "r"(b1))

__device__ __forceinline__ uint32_t sw128(uint32_t off) {
    return off ^ ((off >> 3) & 0x70);
}

// ---------------------------------------------------------------------------
// Conversion kernels: fp32 -> bf16 hi/lo split
// ---------------------------------------------------------------------------
__global__ void convert_hilo_kernel(const float* __restrict__ X,
                                    __nv_bfloat16* __restrict__ H,
                                    __nv_bfloat16* __restrict__ L) {
    int i = blockIdx.x * blockDim.x + threadIdx.x;
    float v = X[i];
    __nv_bfloat16 h = __float2bfloat16(v);
    float r = v - __bfloat162float(h);
    H[i] = h;
    L[i] = __float2bfloat16(r);
}

// W [K][N] row-major -> W^T hi/lo [N][K]
__global__ void transpose_convert_kernel(const float* __restrict__ W,
                                         __nv_bfloat16* __restrict__ Th,
                                         __nv_bfloat16* __restrict__ Tl,
                                         int K, int N) {
    __shared__ float t[32][33];
    int n0 = blockIdx.x * 32, k0 = blockIdx.y * 32;
    int tx = threadIdx.x, ty = threadIdx.y;   // block (32, 8)
#pragma unroll
    for (int i = 0; i < 32; i += 8)
        t[ty + i][tx] = W[(size_t)(k0 + ty + i) * N + n0 + tx];
    __syncthreads();
#pragma unroll
    for (int i = 0; i < 32; i += 8) {
        float v = t[tx][ty + i];
        __nv_bfloat16 h = __float2bfloat16(v);
        float r = v - __bfloat162float(h);
        size_t o = (size_t)(n0 + ty + i) * K + k0 + tx;
        Th[o] = h;
        Tl[o] = __float2bfloat16(r);
    }
}

// ---------------------------------------------------------------------------
// Warp-MMA bf16x3 GEMM: C[M,N] = A@B. A hi/lo [M][K] bf16, B hi/lo [N][K] bf16.
// 128x128 C tile/CTA, 256 thr (8 warps, 4m x 2n), K-chunks 64, cp.async 2-stage.
// mode 0: row-major C. mode 1: (m=b*S+s, n=kv*64+d) -> (b,kv,s,d).
// ---------------------------------------------------------------------------
#define G_TILE   16384            // 128 x 64 bf16 = 16 KB
#define G_STAGE  (4 * G_TILE)     // Ah | Al | Bh | Bl = 64 KB
#define G_SMEM   (2 * G_STAGE)    // 131072 bytes

__global__ void __launch_bounds__(256) gemm_mma_kernel(
    const __nv_bfloat16* __restrict__ Ah, const __nv_bfloat16* __restrict__ Al,
    const __nv_bfloat16* __restrict__ Bh, const __nv_bfloat16* __restrict__ Bl,
    float* __restrict__ C, int N, int K, int mode)
{
    extern __shared__ char smem[];
    const uint32_t sbase = smem_u32(smem);
    const int tid = threadIdx.x;
    const int lane = tid & 31;
    const int wid = tid >> 5;
    const int wm = (wid & 3) * 32;          // warp m offset within tile
    const int wn = (wid >> 2) * 64;         // warp n offset within tile
    const int bm = blockIdx.y * 128;
    const int bn = blockIdx.x * 128;

    const __nv_bfloat16* srcs[4] = {Ah, Al, Bh, Bl};

    // per-thread load slots: 16 x 16B per chunk
    // idx = tid + it*256 over 4096 slots: tile = idx>>10, r = (idx>>3)&127, k8 = idx&7
    auto load_chunk = [&](int c) {
        const uint32_t stage = sbase + (c & 1) * G_STAGE;
        const int koff = c * 64;
#pragma unroll
        for (int it = 0; it < 16; it++) {
            int idx = tid + it * 256;
            int t = idx >> 10;
            int r = (idx >> 3) & 127;
            int k8 = idx & 7;
            int rbase = (t < 2) ? bm : bn;
            const __nv_bfloat16* src = srcs[t] + (size_t)(rbase + r) * K + koff + k8 * 8;
            uint32_t dst = stage + t * G_TILE + sw128(r * 128 + k8 * 16);
            CP_ASYNC16(dst, src);
        }
        CP_COMMIT();
    };

    float acc[2][8][4];
#pragma unroll
    for (int mt = 0; mt < 2; mt++)
#pragma unroll
        for (int nt = 0; nt < 8; nt++)
#pragma unroll
            for (int e = 0; e < 4; e++) acc[mt][nt][e] = 0.0f;

    const int nchunk = K / 64;   // 32
    load_chunk(0);

    // ldmatrix base offsets (lane-dependent, chunk-invariant except ks)
    const int a_row = (lane & 15);
    const int a_cb  = (lane >> 4) * 16;
    const int b_row = (lane & 7) + (lane >> 4) * 8;
    const int b_cb  = ((lane >> 3) & 1) * 16;

    for (int c = 0; c < nchunk; c++) {
        if (c + 1 < nchunk) { load_chunk(c + 1); CP_WAIT1(); }
        else                { CP_WAIT0(); }
        __syncthreads();

        const uint32_t stage = sbase + (c & 1) * G_STAGE;
#pragma unroll
        for (int ks = 0; ks < 4; ks++) {
            uint32_t ah[2][4], al[2][4];
#pragma unroll
            for (int mt = 0; mt < 2; mt++) {
                uint32_t off = sw128((wm + mt * 16 + a_row) * 128 + ks * 32 + a_cb);
                LDSM4(ah[mt], stage + off);
                LDSM4(al[mt], stage + G_TILE + off);
            }
            uint32_t bh[4][4], bl[4][4];
#pragma unroll
            for (int g = 0; g < 4; g++) {
                uint32_t off = sw128((wn + g * 16 + b_row) * 128 + ks * 32 + b_cb);
                LDSM4(bh[g], stage + 2 * G_TILE + off);
                LDSM4(bl[g], stage + 3 * G_TILE + off);
            }
#pragma unroll
            for (int mt = 0; mt < 2; mt++)
#pragma unroll
                for (int nt = 0; nt < 8; nt++) {
                    int g = nt >> 1, p = (nt & 1) * 2;
                    MMA16816(acc[mt][nt], ah[mt], bh[g][p], bh[g][p + 1]);
                    MMA16816(acc[mt][nt], ah[mt], bl[g][p], bl[g][p + 1]);
                    MMA16816(acc[mt][nt], al[mt], bh[g][p], bh[g][p + 1]);
                }
        }
        __syncthreads();
    }

    // Epilogue: direct register -> GMEM stores
    const int cr = lane >> 2;           // 0..7
    const int cc = (lane & 3) * 2;      // 0,2,4,6
#pragma unroll
    for (int mt = 0; mt < 2; mt++) {
#pragma unroll
        for (int nt = 0; nt < 8; nt++) {
            int row0 = bm + wm + mt * 16 + cr;
            int col = bn + wn + nt * 8 + cc;
#pragma unroll
            for (int half = 0; half < 2; half++) {
                int row = row0 + half * 8;
                float2 v = make_float2(acc[mt][nt][half * 2], acc[mt][nt][half * 2 + 1]);
                if (mode == 0) {
                    *(float2*)(C + (size_t)row * N + col) = v;
                } else {
                    int kv = col >> 6, d = col & 63;
                    int b = row >> 11, sl = row & (S_LEN - 1);
                    *(float2*)(C + (((size_t)(b * NKV + kv) * S_LEN + sl) * HDIM) + d) = v;
                }
            }
        }
    }
}

// ---------------------------------------------------------------------------
// RoPE (in-place). Q layout (b,s,h,d); K layout (b,kv,s,d).
// ---------------------------------------------------------------------------
__global__ void rope_q_kernel(float* __restrict__ Q,
                              const float* __restrict__ cosb,
                              const float* __restrict__ sinb)
{
    int idx = blockIdx.x * blockDim.x + threadIdx.x;
    int d = idx & 31;
    int h = (idx >> 5) & 31;
    int m = idx >> 10;
    int s = m & (S_LEN - 1);
    float c = cosb[s * HDIM + d];
    float sn = sinb[s * HDIM + d];
    float* base = Q + (size_t)m * EMBED + h * HDIM;
    float x1 = base[d];
    float x2 = base[d + 32];
    base[d]      = x1 * c - x2 * sn;
    base[d + 32] = x2 * c + x1 * sn;
}

__global__ void rope_k_kernel(float* __restrict__ Kb,
                              const float* __restrict__ cosb,
                              const float* __restrict__ sinb)
{
    int idx = blockIdx.x * blockDim.x + threadIdx.x;
    int d = idx & 31;
    int s = (idx >> 5) & (S_LEN - 1);
    int kvb = idx >> 16;
    float c = cosb[s * HDIM + d];
    float sn = sinb[s * HDIM + d];
    float* base = Kb + ((size_t)kvb * S_LEN + s) * HDIM;
    float x1 = base[d];
    float x2 = base[d + 32];
    base[d]      = x1 * c - x2 * sn;
    base[d + 32] = x2 * c + x1 * sn;
}

// ---------------------------------------------------------------------------
// Flash attention, fp32, causal. (unchanged passing version)
// ---------------------------------------------------------------------------
#define ATT_PAD 68
#define ATT_SMEM (3 * 64 * ATT_PAD * 4)

__global__ void __launch_bounds__(256) attn_kernel(
    const float* __restrict__ Q, const float* __restrict__ Kb,
    const float* __restrict__ Vb, float* __restrict__ O)
{
    extern __shared__ float sm[];
    float* Qs = sm;
    float* Ks = sm + 64 * ATT_PAD;
    float* Vs = sm + 2 * 64 * ATT_PAD;

    const int tid = threadIdx.x;
    const int tx = tid & 15;
    const int ty = tid >> 4;
    const int qtile = blockIdx.x;
    const int h = blockIdx.y;
    const int b = blockIdx.z;
    const int kv = h >> 2;
    const int s0 = qtile * 64;

    const float* Qbase = Q + (size_t)b * S_LEN * EMBED + (size_t)h * HDIM;
    const float* Kbase = Kb + (size_t)(b * NKV + kv) * S_LEN * HDIM;
    const float* Vbase = Vb + (size_t)(b * NKV + kv) * S_LEN * HDIM;

#pragma unroll
    for (int it = 0; it < 4; it++) {
        int f = tid + it * 256;
        int r = f >> 4;
        int c4 = (f & 15) * 4;
        *(float4*)&Qs[r * ATT_PAD + c4] =
            *(const float4*)(Qbase + (size_t)(s0 + r) * EMBED + c4);
    }

    float m_i[4], l_i[4], o_acc[4][4];
#pragma unroll
    for (int i = 0; i < 4; i++) {
        m_i[i] = -1e30f;
        l_i[i] = 0.0f;
#pragma unroll
        for (int j = 0; j < 4; j++) o_acc[i][j] = 0.0f;
    }

    for (int jt = 0; jt <= qtile; jt++) {
#pragma unroll
        for (int it = 0; it < 4; it++) {
            int f = tid + it * 256;
            int r = f >> 4;
            int c4 = (f & 15) * 4;
            *(float4*)&Ks[r * ATT_PAD + c4] =
                *(const float4*)(Kbase + (size_t)(jt * 64 + r) * HDIM + c4);
            *(float4*)&Vs[r * ATT_PAD + c4] =
                *(const float4*)(Vbase + (size_t)(jt * 64 + r) * HDIM + c4);
        }
        __syncthreads();

        float sc[4][4];
#pragma unroll
        for (int i = 0; i < 4; i++)
#pragma unroll
            for (int j = 0; j < 4; j++) sc[i][j] = 0.0f;

#pragma unroll
        for (int kk = 0; kk < 16; kk++) {
            float4 a[4], bv[4];
#pragma unroll
            for (int i = 0; i < 4; i++)
                a[i] = *(float4*)&Qs[(ty * 4 + i) * ATT_PAD + kk * 4];
#pragma unroll
            for (int j = 0; j < 4; j++)
                bv[j] = *(float4*)&Ks[(tx * 4 + j) * ATT_PAD + kk * 4];
#pragma unroll
            for (int i = 0; i < 4; i++)
#pragma unroll
                for (int j = 0; j < 4; j++)
                    sc[i][j] += a[i].x * bv[j].x + a[i].y * bv[j].y +
                                a[i].z * bv[j].z + a[i].w * bv[j].w;
        }

        const float scale = 0.125f;
        if (jt == qtile) {
#pragma unroll
            for (int i = 0; i < 4; i++) {
                int srow = s0 + ty * 4 + i;
#pragma unroll
                for (int j = 0; j < 4; j++) {
                    int tcol = jt * 64 + tx * 4 + j;
                    sc[i][j] = (tcol > srow) ? -1e30f : sc[i][j] * scale;
                }
            }
        } else {
#pragma unroll
            for (int i = 0; i < 4; i++)
#pragma unroll
                for (int j = 0; j < 4; j++) sc[i][j] *= scale;
        }

#pragma unroll
        for (int i = 0; i < 4; i++) {
            float rm = fmaxf(fmaxf(sc[i][0], sc[i][1]), fmaxf(sc[i][2], sc[i][3]));
            rm = fmaxf(rm, __shfl_xor_sync(0xffffffffu, rm, 1));
            rm = fmaxf(rm, __shfl_xor_sync(0xffffffffu, rm, 2));
            rm = fmaxf(rm, __shfl_xor_sync(0xffffffffu, rm, 4));
            rm = fmaxf(rm, __shfl_xor_sync(0xffffffffu, rm, 8));
            float mnew = fmaxf(m_i[i], rm);
            float corr = __expf(m_i[i] - mnew);
            float rs = 0.0f;
#pragma unroll
            for (int j = 0; j < 4; j++) {
                float p = __expf(sc[i][j] - mnew);
                sc[i][j] = p;
                rs += p;
            }
            rs += __shfl_xor_sync(0xffffffffu, rs, 1);
            rs += __shfl_xor_sync(0xffffffffu, rs, 2);
            rs += __shfl_xor_sync(0xffffffffu, rs, 4);
            rs += __shfl_xor_sync(0xffffffffu, rs, 8);
            l_i[i] = l_i[i] * corr + rs;
            m_i[i] = mnew;
#pragma unroll
            for (int j = 0; j < 4; j++) o_acc[i][j] *= corr;
        }

        __syncthreads();
#pragma unroll
        for (int i = 0; i < 4; i++)
            *(float4*)&Ks[(ty * 4 + i) * ATT_PAD + tx * 4] =
                make_float4(sc[i][0], sc[i][1], sc[i][2], sc[i][3]);
        __syncthreads();

#pragma unroll
        for (int t4 = 0; t4 < 16; t4++) {
            float4 a[4], bv[4];
#pragma unroll
            for (int i = 0; i < 4; i++)
                a[i] = *(float4*)&Ks[(ty * 4 + i) * ATT_PAD + t4 * 4];
#pragma unroll
            for (int tt = 0; tt < 4; tt++)
                bv[tt] = *(float4*)&Vs[(t4 * 4 + tt) * ATT_PAD + tx * 4];
#pragma unroll
            for (int i = 0; i < 4; i++) {
                o_acc[i][0] += a[i].x * bv[0].x + a[i].y * bv[1].x + a[i].z * bv[2].x + a[i].w * bv[3].x;
                o_acc[i][1] += a[i].x * bv[0].y + a[i].y * bv[1].y + a[i].z * bv[2].y + a[i].w * bv[3].y;
                o_acc[i][2] += a[i].x * bv[0].z + a[i].y * bv[1].z + a[i].z * bv[2].z + a[i].w * bv[3].z;
                o_acc[i][3] += a[i].x * bv[0].w + a[i].y * bv[1].w + a[i].z * bv[2].w + a[i].w * bv[3].w;
            }
        }
        __syncthreads();
    }

#pragma unroll
    for (int i = 0; i < 4; i++) {
        int srow = s0 + ty * 4 + i;
        float inv = 1.0f / l_i[i];
        float* dst = O + ((size_t)(b * S_LEN + srow) * EMBED) + h * HDIM + tx * 4;
        *(float4*)dst = make_float4(o_acc[i][0] * inv, o_acc[i][1] * inv,
                                    o_acc[i][2] * inv, o_acc[i][3] * inv);
    }
}

// ---------------------------------------------------------------------------
extern "C" void kernel_launch(void* const* d_in, const int* in_sizes, int n_in,
                              void* d_out, int out_size)
{
    const float* x    = (const float*)d_in[0];
    const float* cosb = (const float*)d_in[2];
    const float* sinb = (const float*)d_in[3];
    const float* Wq   = (const float*)d_in[4];
    const float* Wk   = (const float*)d_in[5];
    const float* Wv   = (const float*)d_in[6];
    const float* Wo   = (const float*)d_in[7];

    float* out  = (float*)d_out;
    float* kout = out + OFF_K;
    float* vout = out + OFF_V;

    float *gQ, *gO;
    __nv_bfloat16 *xh, *xl, *oh, *ol;
    __nv_bfloat16 *wqh, *wql, *wkh, *wkl, *wvh, *wvl, *woh, *wol;
    cudaGetSymbolAddress((void**)&gQ, g_Q);
    cudaGetSymbolAddress((void**)&gO, g_O);
    cudaGetSymbolAddress((void**)&xh, g_xh);
    cudaGetSymbolAddress((void**)&xl, g_xl);
    cudaGetSymbolAddress((void**)&oh, g_oh);
    cudaGetSymbolAddress((void**)&ol, g_ol);
    cudaGetSymbolAddress((void**)&wqh, g_wqt_h);
    cudaGetSymbolAddress((void**)&wql, g_wqt_l);
    cudaGetSymbolAddress((void**)&wkh, g_wkt_h);
    cudaGetSymbolAddress((void**)&wkl, g_wkt_l);
    cudaGetSymbolAddress((void**)&wvh, g_wvt_h);
    cudaGetSymbolAddress((void**)&wvl, g_wvt_l);
    cudaGetSymbolAddress((void**)&woh, g_wot_h);
    cudaGetSymbolAddress((void**)&wol, g_wot_l);

    cudaFuncSetAttribute(gemm_mma_kernel, cudaFuncAttributeMaxDynamicSharedMemorySize, G_SMEM);
    cudaFuncSetAttribute(attn_kernel, cudaFuncAttributeMaxDynamicSharedMemorySize, ATT_SMEM);

    // Weight transpose + hi/lo conversion ([K][N] -> [N][K])
    transpose_convert_kernel<<<dim3(EMBED / 32, EMBED / 32), dim3(32, 8)>>>(Wq, wqh, wql, EMBED, EMBED);
    transpose_convert_kernel<<<dim3(KV_N / 32, EMBED / 32), dim3(32, 8)>>>(Wk, wkh, wkl, EMBED, KV_N);
    transpose_convert_kernel<<<dim3(KV_N / 32, EMBED / 32), dim3(32, 8)>>>(Wv, wvh, wvl, EMBED, KV_N);
    transpose_convert_kernel<<<dim3(EMBED / 32, EMBED / 32), dim3(32, 8)>>>(Wo, woh, wol, EMBED, EMBED);

    // Activation conversion
    convert_hilo_kernel<<<(MROWS * EMBED) / 256, 256>>>(x, xh, xl);

    // Projections (warp-MMA bf16x3)
    gemm_mma_kernel<<<dim3(EMBED / 128, MROWS / 128), 256, G_SMEM>>>(xh, xl, wqh, wql, gQ, EMBED, EMBED, 0);
    gemm_mma_kernel<<<dim3(KV_N / 128, MROWS / 128), 256, G_SMEM>>>(xh, xl, wkh, wkl, kout, KV_N, EMBED, 1);
    gemm_mma_kernel<<<dim3(KV_N / 128, MROWS / 128), 256, G_SMEM>>>(xh, xl, wvh, wvl, vout, KV_N, EMBED, 1);

    // RoPE in place (fp32)
    rope_q_kernel<<<(MROWS * NHEAD * 32) / 256, 256>>>(gQ, cosb, sinb);
    rope_k_kernel<<<(BATCH * NKV * S_LEN * 32) / 256, 256>>>(kout, cosb, sinb);

    // Attention (fp32 flash)
    attn_kernel<<<dim3(S_LEN / 64, NHEAD, BATCH), 256, ATT_SMEM>>>(gQ, kout, vout, gO);

    // Output projection
    convert_hilo_kernel<<<(MROWS * EMBED) / 256, 256>>>(gO, oh, ol);
    gemm_mma_kernel<<<dim3(EMBED / 128, MROWS / 128), 256, G_SMEM>>>(oh, ol, woh, wol, out, EMBED, EMBED, 0);
}